// round 1
// baseline (speedup 1.0000x reference)
#include <cuda_runtime.h>

#define N_NODES 50000
#define F 128
#define NE 800000

// ---------------- scratch (device globals: no allocation allowed) ----------
__device__ __align__(16) float g_msg[N_NODES * F];   // 25.6 MB aggregation buffer
__device__ __align__(16) float g_h[N_NODES * F];     // 25.6 MB layer-1 activations
__device__ float g_deg[N_NODES];
__device__ int   g_is64;

// ---------------- edge dtype detection (int64 vs int32, device-side) -------
__global__ void detect_kernel(const int* e32) {
    if (blockIdx.x == 0 && threadIdx.x == 0) {
        // If data is int64 (values < 50000, non-negative), every high word is 0.
        // If int32, odd positions are random node ids; all-32-zero is ~impossible.
        int is64 = 1;
        #pragma unroll
        for (int i = 0; i < 32; ++i) {
            if (e32[2 * i + 1] != 0) { is64 = 0; break; }
        }
        g_is64 = is64;
    }
}

__device__ __forceinline__ int load_idx(const void* edges, int i) {
    if (g_is64) return (int)((const long long*)edges)[i];
    return ((const int*)edges)[i];
}

// ---------------- zeroing -----------------------------------------------
__global__ void zero_kernel(int zero_deg) {
    int i = blockIdx.x * blockDim.x + threadIdx.x;
    int stride = gridDim.x * blockDim.x;
    float4 z = make_float4(0.f, 0.f, 0.f, 0.f);
    float4* m4 = (float4*)g_msg;
    for (int j = i; j < N_NODES * F / 4; j += stride) m4[j] = z;
    if (zero_deg) {
        for (int j = i; j < N_NODES; j += stride) g_deg[j] = 0.f;
    }
}

// ---------------- degree ---------------------------------------------------
__global__ void deg_kernel(const void* __restrict__ edges) {
    int e = blockIdx.x * blockDim.x + threadIdx.x;
    if (e >= NE) return;
    int d = load_idx(edges, NE + e);   // dst = second row of [2, NE]
    atomicAdd(&g_deg[d], 1.0f);
}

// ---------------- edge scatter: msg[dst] += x[src] (warp per edge) ---------
__global__ void scatter_kernel(const float* __restrict__ x,
                               const void* __restrict__ edges) {
    int warps_per_block = blockDim.x >> 5;
    int e = blockIdx.x * warps_per_block + (threadIdx.x >> 5);
    if (e >= NE) return;
    int lane = threadIdx.x & 31;
    int s = load_idx(edges, e);
    int d = load_idx(edges, NE + e);
    float4 v = ((const float4*)(x + (size_t)s * F))[lane];
    float* p = g_msg + (size_t)d * F + lane * 4;
    asm volatile("red.global.add.v4.f32 [%0], {%1,%2,%3,%4};"
                 :: "l"(p), "f"(v.x), "f"(v.y), "f"(v.z), "f"(v.w)
                 : "memory");
}

// ---------------- fused normalize + GEMM + bias (+leaky) -------------------
// out[row, :] = act( ((msg[row]+x[row]) / (deg[row]+1)) @ W + b )
template<int NOUT, int ROWS, bool LEAKY>
__global__ void fused_gemm(const float* __restrict__ x,
                           const float* __restrict__ Wg,
                           const float* __restrict__ bg,
                           float* __restrict__ out) {
    constexpr int TC = NOUT / 4;        // thread-columns (each does 4 cols)
    constexpr int TR = 256 / TC;        // thread-rows    (each does 4 rows)
    static_assert(ROWS == TR * 4, "tile mismatch");
    constexpr int S = F + 4;            // padded smem stride (132)

    extern __shared__ float sm[];
    float* Wsh = sm;                    // F * NOUT
    float* Xs  = sm + F * NOUT;         // ROWS * S

    int t = threadIdx.x;

    // load W (row-major [F][NOUT]) into shared
    for (int i = t; i < F * NOUT / 4; i += 256)
        ((float4*)Wsh)[i] = ((const float4*)Wg)[i];

    // load + normalize X tile into shared
    int row0 = blockIdx.x * ROWS;
    for (int i = t; i < ROWS * (F / 4); i += 256) {
        int r  = i / (F / 4);
        int k4 = i % (F / 4);
        int row = row0 + r;
        float4 v = make_float4(0.f, 0.f, 0.f, 0.f);
        if (row < N_NODES) {
            float4 xv = ((const float4*)(x     + (size_t)row * F))[k4];
            float4 mv = ((const float4*)(g_msg + (size_t)row * F))[k4];
            float rinv = 1.0f / (g_deg[row] + 1.0f);
            v.x = (xv.x + mv.x) * rinv;
            v.y = (xv.y + mv.y) * rinv;
            v.z = (xv.z + mv.z) * rinv;
            v.w = (xv.w + mv.w) * rinv;
        }
        *(float4*)&Xs[r * S + k4 * 4] = v;
    }
    __syncthreads();

    int tc = t % TC;
    int tr = t / TC;

    float acc[4][4];
    #pragma unroll
    for (int r = 0; r < 4; ++r)
        #pragma unroll
        for (int c = 0; c < 4; ++c) acc[r][c] = 0.f;

    #pragma unroll 4
    for (int k = 0; k < F; ++k) {
        float4 wv = *(const float4*)&Wsh[k * NOUT + tc * 4];
        float xr[4];
        #pragma unroll
        for (int r = 0; r < 4; ++r) xr[r] = Xs[(tr * 4 + r) * S + k];
        #pragma unroll
        for (int r = 0; r < 4; ++r) {
            acc[r][0] += xr[r] * wv.x;
            acc[r][1] += xr[r] * wv.y;
            acc[r][2] += xr[r] * wv.z;
            acc[r][3] += xr[r] * wv.w;
        }
    }

    float4 bv = *(const float4*)&bg[tc * 4];
    #pragma unroll
    for (int r = 0; r < 4; ++r) {
        int row = row0 + tr * 4 + r;
        if (row < N_NODES) {
            float4 o;
            o.x = acc[r][0] + bv.x;
            o.y = acc[r][1] + bv.y;
            o.z = acc[r][2] + bv.z;
            o.w = acc[r][3] + bv.w;
            if (LEAKY) {
                o.x = o.x >= 0.f ? o.x : 0.01f * o.x;
                o.y = o.y >= 0.f ? o.y : 0.01f * o.y;
                o.z = o.z >= 0.f ? o.z : 0.01f * o.z;
                o.w = o.w >= 0.f ? o.w : 0.01f * o.w;
            }
            ((float4*)(out + (size_t)row * NOUT))[tc] = o;
        }
    }
}

// ---------------- launch ----------------------------------------------------
extern "C" void kernel_launch(void* const* d_in, const int* in_sizes, int n_in,
                              void* d_out, int out_size) {
    const float* in_feat = (const float*)d_in[0];
    const void*  edges   = d_in[1];          // int64 or int32 (detected on device)
    const float* W1      = (const float*)d_in[2];
    const float* b1      = (const float*)d_in[3];
    const float* W2      = (const float*)d_in[4];
    const float* b2      = (const float*)d_in[5];
    float* out = (float*)d_out;

    // dynamic smem sizes
    const int smem1 = (F * 128 + 32  * (F + 4)) * (int)sizeof(float); // ~80.5 KB
    const int smem2 = (F * 32  + 128 * (F + 4)) * (int)sizeof(float); // ~82 KB
    cudaFuncSetAttribute(fused_gemm<128, 32, true>,
                         cudaFuncAttributeMaxDynamicSharedMemorySize, smem1);
    cudaFuncSetAttribute(fused_gemm<32, 128, false>,
                         cudaFuncAttributeMaxDynamicSharedMemorySize, smem2);

    detect_kernel<<<1, 32>>>((const int*)edges);
    zero_kernel<<<512, 256>>>(1);
    deg_kernel<<<(NE + 255) / 256, 256>>>(edges);

    // layer 1
    {
        int warps_per_block = 8;                     // 256 threads
        int blocks = (NE + warps_per_block - 1) / warps_per_block;
        scatter_kernel<<<blocks, 256>>>(in_feat, edges);
        int gblocks = (N_NODES + 31) / 32;
        fused_gemm<128, 32, true><<<gblocks, 256, smem1>>>(in_feat, W1, b1, g_h);
    }

    // layer 2
    {
        zero_kernel<<<512, 256>>>(0);
        int warps_per_block = 8;
        int blocks = (NE + warps_per_block - 1) / warps_per_block;
        scatter_kernel<<<blocks, 256>>>(g_h, edges);
        int gblocks = (N_NODES + 127) / 128;
        fused_gemm<32, 128, false><<<gblocks, 256, smem2>>>(g_h, W2, b2, out);
    }
}

// round 2
// speedup vs baseline: 11.9800x; 11.9800x over previous
#include <cuda_runtime.h>

#define N_NODES 50000
#define F 128
#define NOUT2 32
#define NE 800000

// ---------------- scratch (device globals: no allocation allowed) ----------
__device__ __align__(16) float g_y1 [N_NODES * F];      // x @ W1
__device__ __align__(16) float g_msg[N_NODES * F];      // y1 self + neighbor sums
__device__ __align__(16) float g_y2 [N_NODES * NOUT2];  // h1 @ W2
__device__ __align__(16) float g_msg2[N_NODES * NOUT2]; // y2 self + neighbor sums
__device__ int g_eidx[2 * NE];                          // int32 edges (src | dst)
__device__ int g_degi[N_NODES];
__device__ int g_is64;

// ---------------- edge dtype detection (int64 vs int32) --------------------
__global__ void detect_kernel(const int* e32) {
    if (threadIdx.x == 0) {
        int is64 = 1;
        #pragma unroll
        for (int i = 0; i < 32; ++i)
            if (e32[2 * i + 1] != 0) { is64 = 0; break; }
        g_is64 = is64;
    }
}

// ---------------- zero degree ----------------------------------------------
__global__ void zerodeg_kernel() {
    int i = blockIdx.x * blockDim.x + threadIdx.x;
    if (i < N_NODES) g_degi[i] = 0;
}

// ---------------- convert edges to int32 + degree histogram ----------------
__global__ void convert_kernel(const void* __restrict__ edges) {
    int i = blockIdx.x * blockDim.x + threadIdx.x;
    if (i >= 2 * NE) return;
    int v;
    if (g_is64) v = (int)((const long long*)edges)[i];
    else        v = ((const int*)edges)[i];
    g_eidx[i] = v;
    if (i >= NE) atomicAdd(&g_degi[v], 1);   // dst half -> in-degree
}

// ---------------- GEMM1: y1 = x @ W1, msg := y1 ----------------------------
// 256 threads, 64 rows x 128 cols per block. Thread tile 8 rows x 4 cols.
__global__ void gemm1_kernel(const float* __restrict__ x,
                             const float* __restrict__ Wg) {
    constexpr int S = F + 4;            // padded stride 132
    extern __shared__ float sm[];
    float* Wsh = sm;                    // 128*128
    float* Xs  = sm + F * F;            // 64*S

    int t = threadIdx.x;
    int row0 = blockIdx.x * 64;

    // W: 4096 float4, 16 per thread
    for (int i = t; i < F * F / 4; i += 256)
        ((float4*)Wsh)[i] = ((const float4*)Wg)[i];

    // X tile: 64 rows x 32 float4
    for (int i = t; i < 64 * (F / 4); i += 256) {
        int r = i >> 5, k4 = i & 31;
        int row = row0 + r;
        float4 v = make_float4(0.f, 0.f, 0.f, 0.f);
        if (row < N_NODES) v = ((const float4*)(x + (size_t)row * F))[k4];
        *(float4*)&Xs[r * S + k4 * 4] = v;
    }
    __syncthreads();

    int tc = t & 31;     // 32 col-groups of 4
    int tr = t >> 5;     // 8 row-groups of 8 (uniform per warp -> Xs broadcast)

    float acc[8][4];
    #pragma unroll
    for (int r = 0; r < 8; ++r)
        #pragma unroll
        for (int c = 0; c < 4; ++c) acc[r][c] = 0.f;

    #pragma unroll 8
    for (int k = 0; k < F; ++k) {
        float4 wv = *(const float4*)&Wsh[k * F + tc * 4];
        float xr[8];
        #pragma unroll
        for (int r = 0; r < 8; ++r) xr[r] = Xs[(tr * 8 + r) * S + k];
        #pragma unroll
        for (int r = 0; r < 8; ++r) {
            acc[r][0] += xr[r] * wv.x;
            acc[r][1] += xr[r] * wv.y;
            acc[r][2] += xr[r] * wv.z;
            acc[r][3] += xr[r] * wv.w;
        }
    }

    #pragma unroll
    for (int r = 0; r < 8; ++r) {
        int row = row0 + tr * 8 + r;
        if (row < N_NODES) {
            float4 o = make_float4(acc[r][0], acc[r][1], acc[r][2], acc[r][3]);
            ((float4*)(g_y1  + (size_t)row * F))[tc] = o;
            ((float4*)(g_msg + (size_t)row * F))[tc] = o;   // self-term init
        }
    }
}

// ---------------- scatter1: msg[dst] += y1[src]  (warp per edge, 128-wide) -
__global__ void scatter1_kernel() {
    int e = blockIdx.x * (blockDim.x >> 5) + (threadIdx.x >> 5);
    if (e >= NE) return;
    int lane = threadIdx.x & 31;
    int s = g_eidx[e];
    int d = g_eidx[NE + e];
    float4 v = ((const float4*)(g_y1 + (size_t)s * F))[lane];
    float* p = g_msg + (size_t)d * F + lane * 4;
    asm volatile("red.global.add.v4.f32 [%0], {%1,%2,%3,%4};"
                 :: "l"(p), "f"(v.x), "f"(v.y), "f"(v.z), "f"(v.w) : "memory");
}

// ---------------- GEMM2: y2 = leaky(msg*rinv + b1) @ W2, msg2 := y2 --------
// 256 threads, 128 rows x 32 cols per block. Thread tile 4 rows x 4 cols.
__global__ void gemm2_kernel(const float* __restrict__ Wg,
                             const float* __restrict__ b1g) {
    constexpr int S = F + 4;
    extern __shared__ float sm[];
    float* Wsh = sm;                    // 128*32
    float* Xs  = sm + F * NOUT2;        // 128*S

    int t = threadIdx.x;
    int row0 = blockIdx.x * 128;

    for (int i = t; i < F * NOUT2 / 4; i += 256)
        ((float4*)Wsh)[i] = ((const float4*)Wg)[i];

    // X tile = layer-1 activations computed on the fly
    for (int i = t; i < 128 * (F / 4); i += 256) {
        int r = i >> 5, k4 = i & 31;
        int row = row0 + r;
        float4 v = make_float4(0.f, 0.f, 0.f, 0.f);
        if (row < N_NODES) {
            float4 mv = ((const float4*)(g_msg + (size_t)row * F))[k4];
            float4 bv = ((const float4*)b1g)[k4];
            float rinv = 1.0f / (float)(g_degi[row] + 1);
            v.x = mv.x * rinv + bv.x;
            v.y = mv.y * rinv + bv.y;
            v.z = mv.z * rinv + bv.z;
            v.w = mv.w * rinv + bv.w;
            v.x = v.x >= 0.f ? v.x : 0.01f * v.x;
            v.y = v.y >= 0.f ? v.y : 0.01f * v.y;
            v.z = v.z >= 0.f ? v.z : 0.01f * v.z;
            v.w = v.w >= 0.f ? v.w : 0.01f * v.w;
        }
        *(float4*)&Xs[r * S + k4 * 4] = v;
    }
    __syncthreads();

    int tc = t & 7;      // 8 col-groups of 4
    int tr = t >> 3;     // 32 row-groups of 4

    float acc[4][4];
    #pragma unroll
    for (int r = 0; r < 4; ++r)
        #pragma unroll
        for (int c = 0; c < 4; ++c) acc[r][c] = 0.f;

    #pragma unroll 8
    for (int k = 0; k < F; ++k) {
        float4 wv = *(const float4*)&Wsh[k * NOUT2 + tc * 4];
        float xr[4];
        #pragma unroll
        for (int r = 0; r < 4; ++r) xr[r] = Xs[(tr * 4 + r) * S + k];
        #pragma unroll
        for (int r = 0; r < 4; ++r) {
            acc[r][0] += xr[r] * wv.x;
            acc[r][1] += xr[r] * wv.y;
            acc[r][2] += xr[r] * wv.z;
            acc[r][3] += xr[r] * wv.w;
        }
    }

    #pragma unroll
    for (int r = 0; r < 4; ++r) {
        int row = row0 + tr * 4 + r;
        if (row < N_NODES) {
            float4 o = make_float4(acc[r][0], acc[r][1], acc[r][2], acc[r][3]);
            ((float4*)(g_y2   + (size_t)row * NOUT2))[tc] = o;
            ((float4*)(g_msg2 + (size_t)row * NOUT2))[tc] = o;  // self-term init
        }
    }
}

// ---------------- scatter2: msg2[dst] += y2[src]  (8 lanes per edge) -------
__global__ void scatter2_kernel() {
    int warp = blockIdx.x * (blockDim.x >> 5) + (threadIdx.x >> 5);
    int lane = threadIdx.x & 31;
    int e = warp * 4 + (lane >> 3);
    if (e >= NE) return;
    int l8 = lane & 7;
    int s = g_eidx[e];
    int d = g_eidx[NE + e];
    float4 v = ((const float4*)(g_y2 + (size_t)s * NOUT2))[l8];
    float* p = g_msg2 + (size_t)d * NOUT2 + l8 * 4;
    asm volatile("red.global.add.v4.f32 [%0], {%1,%2,%3,%4};"
                 :: "l"(p), "f"(v.x), "f"(v.y), "f"(v.z), "f"(v.w) : "memory");
}

// ---------------- epilogue2: out = msg2*rinv + b2 --------------------------
__global__ void epi2_kernel(const float* __restrict__ b2g,
                            float* __restrict__ out) {
    int i = blockIdx.x * blockDim.x + threadIdx.x;   // float4 index
    if (i >= N_NODES * NOUT2 / 4) return;
    int row = i >> 3;
    int c4  = i & 7;
    float rinv = 1.0f / (float)(g_degi[row] + 1);
    float4 mv = ((const float4*)g_msg2)[i];
    float4 bv = ((const float4*)b2g)[c4];
    float4 o;
    o.x = mv.x * rinv + bv.x;
    o.y = mv.y * rinv + bv.y;
    o.z = mv.z * rinv + bv.z;
    o.w = mv.w * rinv + bv.w;
    ((float4*)out)[i] = o;
}

// ---------------- launch ----------------------------------------------------
extern "C" void kernel_launch(void* const* d_in, const int* in_sizes, int n_in,
                              void* d_out, int out_size) {
    const float* in_feat = (const float*)d_in[0];
    const void*  edges   = d_in[1];
    const float* W1      = (const float*)d_in[2];
    const float* b1      = (const float*)d_in[3];
    const float* W2      = (const float*)d_in[4];
    const float* b2      = (const float*)d_in[5];
    float* out = (float*)d_out;

    const int smem1 = (F * F + 64 * (F + 4)) * (int)sizeof(float);        // 99,328 B
    const int smem2 = (F * NOUT2 + 128 * (F + 4)) * (int)sizeof(float);   // 83,968 B
    cudaFuncSetAttribute(gemm1_kernel, cudaFuncAttributeMaxDynamicSharedMemorySize, smem1);
    cudaFuncSetAttribute(gemm2_kernel, cudaFuncAttributeMaxDynamicSharedMemorySize, smem2);

    detect_kernel<<<1, 32>>>((const int*)edges);
    zerodeg_kernel<<<(N_NODES + 255) / 256, 256>>>();
    convert_kernel<<<(2 * NE + 255) / 256, 256>>>(edges);

    gemm1_kernel<<<(N_NODES + 63) / 64, 256, smem1>>>(in_feat, W1);
    scatter1_kernel<<<(NE + 7) / 8, 256>>>();                 // 8 warps/block
    gemm2_kernel<<<(N_NODES + 127) / 128, 256, smem2>>>(W2, b1);
    scatter2_kernel<<<(NE / 4 + 7) / 8, 256>>>();             // 4 edges/warp
    epi2_kernel<<<(N_NODES * NOUT2 / 4 + 255) / 256, 256>>>(b2, out);
}